// round 3
// baseline (speedup 1.0000x reference)
#include <cuda_runtime.h>
#include <cuda_bf16.h>
#include <math.h>

#define NN   50000
#define EE   800000
#define ET   850000          // EE + NN self loops
#define FIN  256
#define HID  64
#define HEADS 4
#define HF   256             // HEADS*HID
#define CLS  32
#define NEG  0.2f

// ---------------- scratch (static device arrays; no cudaMalloc) --------------
__device__ __align__(16) float    g_h1[NN * HF];     // x @ W1
__device__ __align__(16) float    g_out1[NN * HF];   // layer1 output (post elu)
__device__ __align__(16) float    g_h2[NN * CLS];    // out1 @ W2
__device__ __align__(16) float    g_als1[NN * HEADS];
__device__ __align__(16) float    g_ald1[NN * HEADS];
__device__ __align__(16) unsigned g_max1[NN * HEADS];
__device__ __align__(16) float    g_den1[NN * HEADS];
__device__ __align__(16) float    g_ex1[ET * HEADS]; // stored at CSR position
__device__ float    g_als2[NN];
__device__ float    g_ald2[NN];
__device__ unsigned g_max2[NN];
__device__ float    g_den2[NN];
__device__ float    g_ex2[ET];                        // stored at CSR position
__device__ int      g_deg[NN];
__device__ int      g_rowptr[NN + 1];
__device__ int      g_cursor[NN];
__device__ int      g_csr_src[ET];
__device__ int      g_pos[ET];                        // edge -> CSR position
__device__ __align__(8) int2 g_edge[ET];              // (src, dst)
__device__ unsigned g_odd_or;

// order-preserving float<->uint map for atomicMax on floats
__device__ __forceinline__ unsigned fenc(float f) {
    unsigned u = __float_as_uint(f);
    return (u & 0x80000000u) ? ~u : (u | 0x80000000u);
}
__device__ __forceinline__ float fdec(unsigned u) {
    return (u & 0x80000000u) ? __uint_as_float(u ^ 0x80000000u)
                             : __uint_as_float(~u);
}
__device__ __forceinline__ float lrelu(float v) { return v > 0.f ? v : NEG * v; }

// ---------------- init ----------------
__global__ void k_init() {
    int i = blockIdx.x * blockDim.x + threadIdx.x;
    int stride = gridDim.x * blockDim.x;
    if (i == 0) g_odd_or = 0u;
    for (int j = i; j < NN * HEADS; j += stride) {
        g_den1[j] = 0.f;
        g_max1[j] = 0u;           // < fenc(any finite float)
    }
    for (int j = i; j < NN; j += stride) {
        g_den2[j] = 0.f;
        g_max2[j] = 0u;
        g_deg[j]  = 0;
    }
}

// ---------------- detect int64 vs int32 edge_index ---------------------------
// Reads only the first 2*EE 32-bit words (safe under both layouts).
// int64 little-endian: odd words are high words == 0 (indices < 2^31).
// int32: odd words are genuine indices, almost surely nonzero somewhere.
__global__ void k_detect(const unsigned* __restrict__ w) {
    unsigned acc = 0;
    int stride = gridDim.x * blockDim.x;
    for (int i = blockIdx.x * blockDim.x + threadIdx.x; i < EE; i += stride)
        acc |= w[2 * i + 1];
#pragma unroll
    for (int o = 16; o; o >>= 1) acc |= __shfl_xor_sync(0xffffffffu, acc, o);
    __shared__ unsigned sacc[32];
    int lane = threadIdx.x & 31, wid = threadIdx.x >> 5;
    if (!lane) sacc[wid] = acc;
    __syncthreads();
    if (threadIdx.x == 0) {
        unsigned t = 0;
        for (int k = 0; k < (int)(blockDim.x >> 5); k++) t |= sacc[k];
        if (t) atomicOr(&g_odd_or, 1u);
    }
}

__global__ void k_decode(const unsigned* __restrict__ w) {
    int e = blockIdx.x * blockDim.x + threadIdx.x;
    if (e >= ET) return;
    int s, d;
    if (e >= EE) { s = d = e - EE; }
    else if (g_odd_or == 0u) {   // int64 layout
        s = (int)w[2 * e];
        d = (int)w[2 * (EE + e)];
    } else {                     // int32 layout
        s = (int)w[e];
        d = (int)w[EE + e];
    }
    g_edge[e] = make_int2(s, d);
}

// ---------------- GEMM1: C[NN,256] = A[NN,256] @ B[256,256] -------------------
__global__ void k_gemm1(const float* __restrict__ A, const float* __restrict__ B) {
    __shared__ float sA[64][33];
    __shared__ float sB[32][65];
    int tx = threadIdx.x & 15, ty = threadIdx.x >> 4;
    int rowBase = blockIdx.y * 64, colBase = blockIdx.x * 64;
    float acc[4][4] = {};
    for (int k0 = 0; k0 < FIN; k0 += 32) {
#pragma unroll
        for (int i = 0; i < 8; i++) {
            int li = threadIdx.x + i * 256;
            int r = li >> 5, c = li & 31;
            int gr = rowBase + r;
            sA[r][c] = (gr < NN) ? A[gr * FIN + k0 + c] : 0.f;
        }
#pragma unroll
        for (int i = 0; i < 8; i++) {
            int li = threadIdx.x + i * 256;
            int r = li >> 6, c = li & 63;
            sB[r][c] = B[(k0 + r) * HF + colBase + c];
        }
        __syncthreads();
#pragma unroll
        for (int kk = 0; kk < 32; kk++) {
            float a[4], b[4];
#pragma unroll
            for (int i = 0; i < 4; i++) a[i] = sA[ty * 4 + i][kk];
#pragma unroll
            for (int j = 0; j < 4; j++) b[j] = sB[kk][tx * 4 + j];
#pragma unroll
            for (int i = 0; i < 4; i++)
#pragma unroll
                for (int j = 0; j < 4; j++) acc[i][j] += a[i] * b[j];
        }
        __syncthreads();
    }
#pragma unroll
    for (int i = 0; i < 4; i++) {
        int gr = rowBase + ty * 4 + i;
        if (gr < NN) {
#pragma unroll
            for (int j = 0; j < 4; j++)
                g_h1[gr * HF + colBase + tx * 4 + j] = acc[i][j];
        }
    }
}

// ---------------- attention logits layer1: warp per (node, head) -------------
__global__ void k_att1(const float* __restrict__ a_src, const float* __restrict__ a_dst) {
    int w = (blockIdx.x * blockDim.x + threadIdx.x) >> 5;
    int lane = threadIdx.x & 31;
    if (w >= NN * HEADS) return;
    int n = w >> 2, h = w & 3;
    const float* hr = g_h1 + n * HF + h * HID;
    const float* as = a_src + h * HID;
    const float* ad = a_dst + h * HID;
    float v0 = hr[lane], v1 = hr[lane + 32];
    float s = v0 * as[lane] + v1 * as[lane + 32];
    float d = v0 * ad[lane] + v1 * ad[lane + 32];
#pragma unroll
    for (int o = 16; o; o >>= 1) {
        s += __shfl_xor_sync(0xffffffffu, s, o);
        d += __shfl_xor_sync(0xffffffffu, d, o);
    }
    if (!lane) { g_als1[n * HEADS + h] = s; g_ald1[n * HEADS + h] = d; }
}

// ---------------- edge pass 1: segment max per head + degree count -----------
__global__ void k_edge_max1() {
    int e = blockIdx.x * blockDim.x + threadIdx.x;
    if (e >= ET) return;
    int2 ed = g_edge[e];
    float4 as = ((const float4*)g_als1)[ed.x];
    float4 ad = ((const float4*)g_ald1)[ed.y];
    unsigned* mx = g_max1 + ed.y * HEADS;
    atomicMax(mx + 0, fenc(lrelu(as.x + ad.x)));
    atomicMax(mx + 1, fenc(lrelu(as.y + ad.y)));
    atomicMax(mx + 2, fenc(lrelu(as.z + ad.z)));
    atomicMax(mx + 3, fenc(lrelu(as.w + ad.w)));
    atomicAdd(&g_deg[ed.y], 1);
}

// ---------------- single-block scan: rowptr from degrees ---------------------
__global__ void k_scan() {
    __shared__ int sdata[1024];
    __shared__ int soff;
    if (threadIdx.x == 0) { soff = 0; g_rowptr[0] = 0; }
    __syncthreads();
    for (int base = 0; base < NN; base += 1024) {
        int i = base + threadIdx.x;
        int v = (i < NN) ? g_deg[i] : 0;
        sdata[threadIdx.x] = v;
        __syncthreads();
        for (int d = 1; d < 1024; d <<= 1) {
            int t = (threadIdx.x >= d) ? sdata[threadIdx.x - d] : 0;
            __syncthreads();
            sdata[threadIdx.x] += t;
            __syncthreads();
        }
        int incl = sdata[threadIdx.x] + soff;
        if (i < NN) g_rowptr[i + 1] = incl;
        __syncthreads();
        if (threadIdx.x == 1023) soff = incl;
        __syncthreads();
    }
}

__global__ void k_cursor() {
    int i = blockIdx.x * blockDim.x + threadIdx.x;
    if (i < NN) g_cursor[i] = g_rowptr[i];
}

// ---------------- edge pass 2: exp + denom + CSR scatter ---------------------
__global__ void k_edge_exp1() {
    int e = blockIdx.x * blockDim.x + threadIdx.x;
    if (e >= ET) return;
    int2 ed = g_edge[e];
    int pos = atomicAdd(&g_cursor[ed.y], 1);
    g_csr_src[pos] = ed.x;
    g_pos[e] = pos;
    float4 as = ((const float4*)g_als1)[ed.x];
    float4 ad = ((const float4*)g_ald1)[ed.y];
    const unsigned* mx = g_max1 + ed.y * HEADS;
    float e0 = expf(lrelu(as.x + ad.x) - fdec(mx[0]));
    float e1 = expf(lrelu(as.y + ad.y) - fdec(mx[1]));
    float e2 = expf(lrelu(as.z + ad.z) - fdec(mx[2]));
    float e3 = expf(lrelu(as.w + ad.w) - fdec(mx[3]));
    ((float4*)g_ex1)[pos] = make_float4(e0, e1, e2, e3);
    float* dn = g_den1 + ed.y * HEADS;
    atomicAdd(dn + 0, e0);
    atomicAdd(dn + 1, e1);
    atomicAdd(dn + 2, e2);
    atomicAdd(dn + 3, e3);
}

// ---------------- aggregate layer1 (gather, no atomics) + bias + elu ---------
__global__ void k_agg1(const float* __restrict__ b1) {
    int n = blockIdx.x;
    int tid = threadIdx.x;
    int h = tid >> 6;
    int beg = g_rowptr[n], end = g_rowptr[n + 1];
    float acc = 0.f;
    for (int k = beg; k < end; k++) {
        int s = g_csr_src[k];
        float ex = g_ex1[k * HEADS + h];
        acc += ex * g_h1[s * HF + tid];
    }
    float v = acc * __fdividef(1.f, g_den1[n * HEADS + h]) + b1[tid];
    g_out1[n * HF + tid] = v > 0.f ? v : expm1f(v);
}

// ---------------- GEMM2: h2[NN,32] = out1[NN,256] @ W2[256,32] ---------------
__global__ void k_gemm2(const float* __restrict__ W2) {
    __shared__ float sW[FIN * CLS];
    for (int i = threadIdx.x; i < FIN * CLS; i += 256) sW[i] = W2[i];
    __syncthreads();
    int lane = threadIdx.x & 31, w = threadIdx.x >> 5;
    int n = blockIdx.x * 8 + w;
    if (n >= NN) return;
    const float* xr = g_out1 + n * FIN;
    float xv[8];
#pragma unroll
    for (int j = 0; j < 8; j++) xv[j] = xr[j * 32 + lane];
    float acc = 0.f;
#pragma unroll
    for (int j = 0; j < 8; j++)
#pragma unroll
        for (int t = 0; t < 32; t++)
            acc += __shfl_sync(0xffffffffu, xv[j], t) * sW[(j * 32 + t) * CLS + lane];
    g_h2[n * CLS + lane] = acc;
}

// ---------------- attention logits layer2: warp per node ---------------------
__global__ void k_att2(const float* __restrict__ a_src, const float* __restrict__ a_dst) {
    int w = (blockIdx.x * blockDim.x + threadIdx.x) >> 5;
    int lane = threadIdx.x & 31;
    if (w >= NN) return;
    float v = g_h2[w * CLS + lane];
    float s = v * a_src[lane], d = v * a_dst[lane];
#pragma unroll
    for (int o = 16; o; o >>= 1) {
        s += __shfl_xor_sync(0xffffffffu, s, o);
        d += __shfl_xor_sync(0xffffffffu, d, o);
    }
    if (!lane) { g_als2[w] = s; g_ald2[w] = d; }
}

__global__ void k_edge_max2() {
    int e = blockIdx.x * blockDim.x + threadIdx.x;
    if (e >= ET) return;
    int2 ed = g_edge[e];
    float v = lrelu(g_als2[ed.x] + g_ald2[ed.y]);
    atomicMax(&g_max2[ed.y], fenc(v));
}

__global__ void k_edge_exp2() {
    int e = blockIdx.x * blockDim.x + threadIdx.x;
    if (e >= ET) return;
    int2 ed = g_edge[e];
    float v = lrelu(g_als2[ed.x] + g_ald2[ed.y]);
    float ex = expf(v - fdec(g_max2[ed.y]));
    g_ex2[g_pos[e]] = ex;
    atomicAdd(&g_den2[ed.y], ex);
}

// ---------------- aggregate layer2 + bias + fused log_softmax ----------------
__global__ void k_agg2(const float* __restrict__ b2, float* __restrict__ out) {
    int w = (blockIdx.x * blockDim.x + threadIdx.x) >> 5;
    int lane = threadIdx.x & 31;
    if (w >= NN) return;
    int beg = g_rowptr[w], end = g_rowptr[w + 1];
    float acc = 0.f;
    for (int k = beg; k < end; k++) {
        int s = g_csr_src[k];
        acc += g_ex2[k] * g_h2[s * CLS + lane];
    }
    float v = acc * __fdividef(1.f, g_den2[w]) + b2[lane];
    float m = v;
#pragma unroll
    for (int o = 16; o; o >>= 1) m = fmaxf(m, __shfl_xor_sync(0xffffffffu, m, o));
    float ex = expf(v - m);
    float sum = ex;
#pragma unroll
    for (int o = 16; o; o >>= 1) sum += __shfl_xor_sync(0xffffffffu, sum, o);
    out[w * CLS + lane] = v - m - logf(sum);
}

// -----------------------------------------------------------------------------
extern "C" void kernel_launch(void* const* d_in, const int* in_sizes, int n_in,
                              void* d_out, int out_size) {
    const float*    x      = (const float*)d_in[0];
    const unsigned* ei     = (const unsigned*)d_in[1];
    const float*    W1     = (const float*)d_in[2];
    const float*    a_src1 = (const float*)d_in[3];
    const float*    a_dst1 = (const float*)d_in[4];
    const float*    b1     = (const float*)d_in[5];
    const float*    W2     = (const float*)d_in[6];
    const float*    a_src2 = (const float*)d_in[7];
    const float*    a_dst2 = (const float*)d_in[8];
    const float*    b2     = (const float*)d_in[9];
    float*          out    = (float*)d_out;

    const int EB = (ET + 255) / 256;           // edge-parallel blocks

    k_init<<<512, 256>>>();
    k_detect<<<256, 256>>>(ei);
    k_decode<<<EB, 256>>>(ei);
    k_gemm1<<<dim3(HF / 64, (NN + 63) / 64), 256>>>(x, W1);
    k_att1<<<(NN * HEADS * 32 + 255) / 256, 256>>>(a_src1, a_dst1);
    k_edge_max1<<<EB, 256>>>();
    k_scan<<<1, 1024>>>();
    k_cursor<<<(NN + 255) / 256, 256>>>();
    k_edge_exp1<<<EB, 256>>>();
    k_agg1<<<NN, 256>>>(b1);
    k_gemm2<<<NN / 8, 256>>>(W2);
    k_att2<<<(NN * 32 + 255) / 256, 256>>>(a_src2, a_dst2);
    k_edge_max2<<<EB, 256>>>();
    k_edge_exp2<<<EB, 256>>>();
    k_agg2<<<(NN * 32 + 255) / 256, 256>>>(b2, out);
}

// round 4
// speedup vs baseline: 1.1273x; 1.1273x over previous
#include <cuda_runtime.h>
#include <cuda_bf16.h>
#include <math.h>

#define NN   50000
#define EE   800000
#define ET   850000          // EE + NN self loops
#define FIN  256
#define HID  64
#define HEADS 4
#define HF   256             // HEADS*HID
#define CLS  32
#define NEG  0.2f

// ---------------- scratch (static device arrays; no cudaMalloc) --------------
__device__ __align__(16) float    g_h1[NN * HF];     // x @ W1
__device__ __align__(16) float    g_out1[NN * HF];   // layer1 output (post elu)
__device__ __align__(16) float    g_h2[NN * CLS];    // out1 @ W2
__device__ __align__(16) float    g_als1[NN * HEADS];
__device__ __align__(16) float    g_ald1[NN * HEADS];
__device__ __align__(16) float    g_den1[NN * HEADS];
__device__ __align__(16) float    g_ex1[ET * HEADS]; // stored at CSR position
__device__ float    g_als2[NN];
__device__ float    g_ald2[NN];
__device__ float    g_den2[NN];
__device__ float    g_ex2[ET];                        // stored at CSR position
__device__ int      g_deg[NN];
__device__ int      g_rowptr[NN + 1];
__device__ int      g_cursor[NN];
__device__ int      g_csr_src[ET];
__device__ int      g_pos[ET];                        // edge -> CSR position
__device__ __align__(8) int2 g_edge[ET];              // (src, dst)
__device__ unsigned g_odd_or;

__device__ __forceinline__ float lrelu(float v) { return v > 0.f ? v : NEG * v; }

// ---------------- init ----------------
__global__ void k_init() {
    int i = blockIdx.x * blockDim.x + threadIdx.x;
    int stride = gridDim.x * blockDim.x;
    if (i == 0) g_odd_or = 0u;
    for (int j = i; j < NN * HEADS; j += stride) g_den1[j] = 0.f;
    for (int j = i; j < NN; j += stride) { g_den2[j] = 0.f; g_deg[j] = 0; }
}

// ---------------- detect int64 vs int32 edge_index ---------------------------
__global__ void k_detect(const unsigned* __restrict__ w) {
    unsigned acc = 0;
    int stride = gridDim.x * blockDim.x;
    for (int i = blockIdx.x * blockDim.x + threadIdx.x; i < EE; i += stride)
        acc |= w[2 * i + 1];
#pragma unroll
    for (int o = 16; o; o >>= 1) acc |= __shfl_xor_sync(0xffffffffu, acc, o);
    __shared__ unsigned sacc[32];
    int lane = threadIdx.x & 31, wid = threadIdx.x >> 5;
    if (!lane) sacc[wid] = acc;
    __syncthreads();
    if (threadIdx.x == 0) {
        unsigned t = 0;
        for (int k = 0; k < (int)(blockDim.x >> 5); k++) t |= sacc[k];
        if (t) atomicOr(&g_odd_or, 1u);
    }
}

// decode edges (+ self loops) and count in-degree
__global__ void k_decode(const unsigned* __restrict__ w) {
    int e = blockIdx.x * blockDim.x + threadIdx.x;
    if (e >= ET) return;
    int s, d;
    if (e >= EE) { s = d = e - EE; }
    else if (g_odd_or == 0u) {   // int64 layout
        s = (int)w[2 * e];
        d = (int)w[2 * (EE + e)];
    } else {                     // int32 layout
        s = (int)w[e];
        d = (int)w[EE + e];
    }
    g_edge[e] = make_int2(s, d);
    atomicAdd(&g_deg[d], 1);
}

// ---------------- GEMM1: 128x128 tile, 8x8 per thread, TK=16 -----------------
__global__ void __launch_bounds__(256, 2) k_gemm1(const float* __restrict__ A,
                                                  const float* __restrict__ B) {
    __shared__ float sA[16][128];   // [k][m]
    __shared__ float sB[16][128];   // [k][n]
    int tid = threadIdx.x;
    int tx = tid & 15, ty = tid >> 4;         // 16x16 thread grid
    int rowBase = blockIdx.y * 128, colBase = blockIdx.x * 128;
    float acc[8][8] = {};
    float ra[8], rb[8];

    // A-load mapping: each thread loads 2 float4 (8 floats along k) for one row
    int aRow = tid >> 1;                      // 0..127
    int aK   = (tid & 1) * 8;                 // 0 or 8
    // B-load mapping: row r = tid>>4 (0..15), cols (tid&15)*8, two float4
    int bRow = tid >> 4;
    int bCol = (tid & 15) * 8;

    for (int k0 = 0; k0 < FIN; k0 += 16) {
        int gr = rowBase + aRow;
        float4 a0, a1;
        if (gr < NN) {
            const float4* ap = (const float4*)(A + gr * FIN + k0 + aK);
            a0 = ap[0]; a1 = ap[1];
        } else {
            a0 = make_float4(0.f, 0.f, 0.f, 0.f); a1 = a0;
        }
        sA[aK + 0][aRow] = a0.x; sA[aK + 1][aRow] = a0.y;
        sA[aK + 2][aRow] = a0.z; sA[aK + 3][aRow] = a0.w;
        sA[aK + 4][aRow] = a1.x; sA[aK + 5][aRow] = a1.y;
        sA[aK + 6][aRow] = a1.z; sA[aK + 7][aRow] = a1.w;

        const float4* bp = (const float4*)(B + (k0 + bRow) * HF + colBase + bCol);
        ((float4*)&sB[bRow][bCol])[0] = bp[0];
        ((float4*)&sB[bRow][bCol])[1] = bp[1];
        __syncthreads();

#pragma unroll
        for (int kk = 0; kk < 16; kk++) {
            ((float4*)ra)[0] = ((const float4*)&sA[kk][ty * 8])[0];
            ((float4*)ra)[1] = ((const float4*)&sA[kk][ty * 8])[1];
            ((float4*)rb)[0] = ((const float4*)&sB[kk][tx * 8])[0];
            ((float4*)rb)[1] = ((const float4*)&sB[kk][tx * 8])[1];
#pragma unroll
            for (int i = 0; i < 8; i++)
#pragma unroll
                for (int j = 0; j < 8; j++) acc[i][j] += ra[i] * rb[j];
        }
        __syncthreads();
    }
#pragma unroll
    for (int i = 0; i < 8; i++) {
        int gr = rowBase + ty * 8 + i;
        if (gr < NN) {
            float4* op = (float4*)(g_h1 + gr * HF + colBase + tx * 8);
            op[0] = make_float4(acc[i][0], acc[i][1], acc[i][2], acc[i][3]);
            op[1] = make_float4(acc[i][4], acc[i][5], acc[i][6], acc[i][7]);
        }
    }
}

// ---------------- attention logits layer1: warp per (node, head) -------------
__global__ void k_att1(const float* __restrict__ a_src, const float* __restrict__ a_dst) {
    int w = (blockIdx.x * blockDim.x + threadIdx.x) >> 5;
    int lane = threadIdx.x & 31;
    if (w >= NN * HEADS) return;
    int n = w >> 2, h = w & 3;
    const float* hr = g_h1 + n * HF + h * HID;
    const float* as = a_src + h * HID;
    const float* ad = a_dst + h * HID;
    float v0 = hr[lane], v1 = hr[lane + 32];
    float s = v0 * as[lane] + v1 * as[lane + 32];
    float d = v0 * ad[lane] + v1 * ad[lane + 32];
#pragma unroll
    for (int o = 16; o; o >>= 1) {
        s += __shfl_xor_sync(0xffffffffu, s, o);
        d += __shfl_xor_sync(0xffffffffu, d, o);
    }
    if (!lane) { g_als1[n * HEADS + h] = s; g_ald1[n * HEADS + h] = d; }
}

// ---------------- single-block scan: rowptr + cursor from degrees ------------
__global__ void k_scan() {
    __shared__ int sdata[1024];
    __shared__ int soff;
    if (threadIdx.x == 0) { soff = 0; g_rowptr[0] = 0; }
    __syncthreads();
    for (int base = 0; base < NN; base += 1024) {
        int i = base + threadIdx.x;
        int v = (i < NN) ? g_deg[i] : 0;
        sdata[threadIdx.x] = v;
        __syncthreads();
        for (int d = 1; d < 1024; d <<= 1) {
            int t = (threadIdx.x >= d) ? sdata[threadIdx.x - d] : 0;
            __syncthreads();
            sdata[threadIdx.x] += t;
            __syncthreads();
        }
        int incl = sdata[threadIdx.x] + soff;
        if (i < NN) { g_rowptr[i + 1] = incl; g_cursor[i] = incl - v; }
        __syncthreads();
        if (threadIdx.x == 1023) soff = incl;
        __syncthreads();
    }
}

// ---------------- edge pass 1: exp (no max shift) + denom + CSR scatter ------
__global__ void k_edge_exp1() {
    int e = blockIdx.x * blockDim.x + threadIdx.x;
    if (e >= ET) return;
    int2 ed = g_edge[e];
    int pos = atomicAdd(&g_cursor[ed.y], 1);
    g_csr_src[pos] = ed.x;
    g_pos[e] = pos;
    float4 as = ((const float4*)g_als1)[ed.x];
    float4 ad = ((const float4*)g_ald1)[ed.y];
    float e0 = __expf(lrelu(as.x + ad.x));
    float e1 = __expf(lrelu(as.y + ad.y));
    float e2 = __expf(lrelu(as.z + ad.z));
    float e3 = __expf(lrelu(as.w + ad.w));
    ((float4*)g_ex1)[pos] = make_float4(e0, e1, e2, e3);
    float* dn = g_den1 + ed.y * HEADS;
    atomicAdd(dn + 0, e0);
    atomicAdd(dn + 1, e1);
    atomicAdd(dn + 2, e2);
    atomicAdd(dn + 3, e3);
}

// ---------------- aggregate layer1 (gather, no atomics) + bias + elu ---------
__global__ void k_agg1(const float* __restrict__ b1) {
    int n = blockIdx.x;
    int tid = threadIdx.x;
    int h = tid >> 6;
    int beg = g_rowptr[n], end = g_rowptr[n + 1];
    float acc = 0.f;
    for (int k = beg; k < end; k++) {
        int s = g_csr_src[k];
        float ex = g_ex1[k * HEADS + h];
        acc += ex * g_h1[s * HF + tid];
    }
    float v = acc * __fdividef(1.f, g_den1[n * HEADS + h]) + b1[tid];
    g_out1[n * HF + tid] = v > 0.f ? v : expm1f(v);
}

// ---------------- GEMM2: h2[NN,32] = out1[NN,256] @ W2[256,32] ---------------
__global__ void k_gemm2(const float* __restrict__ W2) {
    __shared__ float sW[FIN * CLS];
    for (int i = threadIdx.x; i < FIN * CLS; i += 256) sW[i] = W2[i];
    __syncthreads();
    int lane = threadIdx.x & 31, w = threadIdx.x >> 5;
    int n = blockIdx.x * 8 + w;
    if (n >= NN) return;
    const float* xr = g_out1 + n * FIN;
    float xv[8];
#pragma unroll
    for (int j = 0; j < 8; j++) xv[j] = xr[j * 32 + lane];
    float acc = 0.f;
#pragma unroll
    for (int j = 0; j < 8; j++)
#pragma unroll
        for (int t = 0; t < 32; t++)
            acc += __shfl_sync(0xffffffffu, xv[j], t) * sW[(j * 32 + t) * CLS + lane];
    g_h2[n * CLS + lane] = acc;
}

// ---------------- attention logits layer2: warp per node ---------------------
__global__ void k_att2(const float* __restrict__ a_src, const float* __restrict__ a_dst) {
    int w = (blockIdx.x * blockDim.x + threadIdx.x) >> 5;
    int lane = threadIdx.x & 31;
    if (w >= NN) return;
    float v = g_h2[w * CLS + lane];
    float s = v * a_src[lane], d = v * a_dst[lane];
#pragma unroll
    for (int o = 16; o; o >>= 1) {
        s += __shfl_xor_sync(0xffffffffu, s, o);
        d += __shfl_xor_sync(0xffffffffu, d, o);
    }
    if (!lane) { g_als2[w] = s; g_ald2[w] = d; }
}

// ---------------- edge pass 2: exp (no max shift) + denom --------------------
__global__ void k_edge_exp2() {
    int e = blockIdx.x * blockDim.x + threadIdx.x;
    if (e >= ET) return;
    int2 ed = g_edge[e];
    float ex = __expf(lrelu(g_als2[ed.x] + g_ald2[ed.y]));
    g_ex2[g_pos[e]] = ex;
    atomicAdd(&g_den2[ed.y], ex);
}

// ---------------- aggregate layer2 + bias + fused log_softmax ----------------
__global__ void k_agg2(const float* __restrict__ b2, float* __restrict__ out) {
    int w = (blockIdx.x * blockDim.x + threadIdx.x) >> 5;
    int lane = threadIdx.x & 31;
    if (w >= NN) return;
    int beg = g_rowptr[w], end = g_rowptr[w + 1];
    float acc = 0.f;
    for (int k = beg; k < end; k++) {
        int s = g_csr_src[k];
        acc += g_ex2[k] * g_h2[s * CLS + lane];
    }
    float v = acc * __fdividef(1.f, g_den2[w]) + b2[lane];
    float m = v;
#pragma unroll
    for (int o = 16; o; o >>= 1) m = fmaxf(m, __shfl_xor_sync(0xffffffffu, m, o));
    float ex = __expf(v - m);
    float sum = ex;
#pragma unroll
    for (int o = 16; o; o >>= 1) sum += __shfl_xor_sync(0xffffffffu, sum, o);
    out[w * CLS + lane] = v - m - logf(sum);
}

// -----------------------------------------------------------------------------
extern "C" void kernel_launch(void* const* d_in, const int* in_sizes, int n_in,
                              void* d_out, int out_size) {
    const float*    x      = (const float*)d_in[0];
    const unsigned* ei     = (const unsigned*)d_in[1];
    const float*    W1     = (const float*)d_in[2];
    const float*    a_src1 = (const float*)d_in[3];
    const float*    a_dst1 = (const float*)d_in[4];
    const float*    b1     = (const float*)d_in[5];
    const float*    W2     = (const float*)d_in[6];
    const float*    a_src2 = (const float*)d_in[7];
    const float*    a_dst2 = (const float*)d_in[8];
    const float*    b2     = (const float*)d_in[9];
    float*          out    = (float*)d_out;

    const int EB = (ET + 255) / 256;           // edge-parallel blocks

    k_init<<<512, 256>>>();
    k_detect<<<256, 256>>>(ei);
    k_decode<<<EB, 256>>>(ei);
    k_gemm1<<<dim3(2, (NN + 127) / 128), 256>>>(x, W1);
    k_att1<<<(NN * HEADS * 32 + 255) / 256, 256>>>(a_src1, a_dst1);
    k_scan<<<1, 1024>>>();
    k_edge_exp1<<<EB, 256>>>();
    k_agg1<<<NN, 256>>>(b1);
    k_gemm2<<<NN / 8, 256>>>(W2);
    k_att2<<<(NN * 32 + 255) / 256, 256>>>(a_src2, a_dst2);
    k_edge_exp2<<<EB, 256>>>();
    k_agg2<<<(NN * 32 + 255) / 256, 256>>>(b2, out);
}